// round 9
// baseline (speedup 1.0000x reference)
#include <cuda_runtime.h>

#define TB 256
typedef unsigned long long ull;

__device__ __forceinline__ float fsig(float x) {
    float e = __expf(-x);
    return __fdividef(1.0f, 1.0f + e);
}
__device__ __forceinline__ float ftanh(float x) {
    float e = __expf(2.0f * x);
    return 1.0f - __fdividef(2.0f, e + 1.0f);
}
__device__ __forceinline__ ull pack2(float lo, float hi) {
    ull r; asm("mov.b64 %0, {%1, %2};" : "=l"(r) : "f"(lo), "f"(hi)); return r;
}
__device__ __forceinline__ ull dup2(float v) {
    ull r; asm("mov.b64 %0, {%1, %1};" : "=l"(r) : "f"(v)); return r;
}
__device__ __forceinline__ void unpack2(ull v, float& lo, float& hi) {
    asm("mov.b64 {%0, %1}, %2;" : "=f"(lo), "=f"(hi) : "l"(v));
}
#define FMA2(acc, w, a) asm("fma.rn.f32x2 %0, %1, %2, %0;" : "+l"(acc) : "l"(w), "l"(a))

// named barriers: pair of LSTM warps (64 thr), whole group (128 thr)
#define PAIRBAR(g)  asm volatile("bar.sync %0, 64;"  :: "r"((g) + 1) : "memory")
#define GROUPBAR(g) asm volatile("bar.sync %0, 128;" :: "r"((g) + 3) : "memory")

// smem float offsets
#define OFF_W   0      // ull2[2048] gate-pair weights [m_global*32 + j]
#define OFF_B   8192   // ull2[32] bias pairs
#define OFF_CO  8320   // float4[32] coW
#define OFF_CF  8448   // float[32*8] cf rows
#define OFF_COB 8704
#define OFF_K   8708   // 16 runtime Kalman consts (pad to 8736)
#define OFF_GRP 8736
// per-group layout
#define GXR   0        // X ring: 6 slots x [6 k][64 el] = 2304
#define GFEAT 2304     // [32 m][64 el]
#define GH    4352     // [32 j][64 el]
#define GC    6400     // [32 j][64 el]
#define GCMD  8448     // [2 warp][4 cmd][64 el] = 512
#define GRP_FLOATS 8960
#define SMEM_FLOATS (8736 + 2 * 8960)

#define KC_GHX 0
#define KC_GHY 3
#define KC_R   6
#define KC_GT  9

extern __shared__ float s_raw[];

__global__ void __launch_bounds__(TB, 2) kalman_lstm_kernel(
    const float* __restrict__ hist,
    const float* __restrict__ p_psx, const float* __restrict__ p_psy,
    const float* __restrict__ p_vsx, const float* __restrict__ p_vsy,
    const float* __restrict__ p_asx, const float* __restrict__ p_asy,
    const float* __restrict__ p_jerk, const float* __restrict__ p_coefG,
    const float* __restrict__ p_GR,
    const float* __restrict__ cfW, const float* __restrict__ cfb,
    const float* __restrict__ Wih, const float* __restrict__ Whh,
    const float* __restrict__ bih, const float* __restrict__ bhh,
    const float* __restrict__ coW, const float* __restrict__ cob,
    float* __restrict__ out,
    int B, int LP)
{
    const int tid = threadIdx.x;
    const int warpid = tid >> 5;
    const int lane = tid & 31;

    // ---- stage weights/consts ----
    for (int idx = tid; idx < 2048; idx += TB) {
        int mg = idx >> 5;
        int j  = idx & 31;
        const float* W = (mg < 32) ? Wih : Whh;
        int m = mg & 31;
        ulonglong2 v;
        v.x = pack2(W[j * 32 + m],        W[(32 + j) * 32 + m]);
        v.y = pack2(W[(64 + j) * 32 + m], W[(96 + j) * 32 + m]);
        reinterpret_cast<ulonglong2*>(s_raw + OFF_W)[idx] = v;
    }
    if (tid < 32) {
        int j = tid;
        ulonglong2 b;
        b.x = pack2(bih[j] + bhh[j],           bih[32 + j] + bhh[32 + j]);
        b.y = pack2(bih[64 + j] + bhh[64 + j], bih[96 + j] + bhh[96 + j]);
        reinterpret_cast<ulonglong2*>(s_raw + OFF_B)[j] = b;
        reinterpret_cast<float4*>(s_raw + OFF_CO)[j] = make_float4(
            coW[j], coW[32 + j], coW[64 + j], coW[96 + j]);
#pragma unroll
        for (int k = 0; k < 6; k++) s_raw[OFF_CF + j * 8 + k] = cfW[j * 6 + k];
        s_raw[OFF_CF + j * 8 + 6] = cfb[j];
        s_raw[OFF_CF + j * 8 + 7] = 0.0f;
    }
    if (tid == 32) {
        const float g0 = (float)(0.2 * 0.2 * 0.2 / 6.0), g1 = 0.02f, g2 = 0.2f;
        float tg0 = tanhf(p_coefG[0]), tg1 = tanhf(p_coefG[1]), tg2 = tanhf(p_coefG[2]);
        float tg3 = tanhf(p_coefG[3]), tg4 = tanhf(p_coefG[4]), tg5 = tanhf(p_coefG[5]);
        float jk0 = p_jerk[0], jk1 = p_jerk[1];
        s_raw[OFF_K + KC_GHX + 0] = g0 * tg0 * jk0;
        s_raw[OFF_K + KC_GHX + 1] = g1 * tg1 * jk0;
        s_raw[OFF_K + KC_GHX + 2] = g2 * tg2 * jk0;
        s_raw[OFF_K + KC_GHY + 0] = g0 * tg3 * jk1;
        s_raw[OFF_K + KC_GHY + 1] = g1 * tg4 * jk1;
        s_raw[OFF_K + KC_GHY + 2] = g2 * tg5 * jk1;
        float gr0 = p_GR[0], gr1 = p_GR[1];
        s_raw[OFF_K + KC_R + 0] = gr0 * gr0;
        s_raw[OFF_K + KC_R + 1] = gr0 * gr1;
        s_raw[OFF_K + KC_R + 2] = gr1 * gr1;
        s_raw[OFF_K + KC_GT + 0] = g0 * tg0;
        s_raw[OFF_K + KC_GT + 1] = g1 * tg1;
        s_raw[OFF_K + KC_GT + 2] = g2 * tg2;
        s_raw[OFF_K + KC_GT + 3] = g0 * tg3;
        s_raw[OFF_K + KC_GT + 4] = g1 * tg4;
        s_raw[OFF_K + KC_GT + 5] = g2 * tg5;
        s_raw[OFF_COB + 0] = cob[0]; s_raw[OFF_COB + 1] = cob[1];
        s_raw[OFF_COB + 2] = cob[2]; s_raw[OFF_COB + 3] = cob[3];
    }

    const float dt = 0.2f, hd2 = 0.02f;
    const float g0 = (float)(0.2 * 0.2 * 0.2 / 6.0);
    const float g1 = 0.02f;
    const float g2 = 0.2f;
    const float2* hist2 = reinterpret_cast<const float2*>(hist);

    float X[6], P[6][6];
    int e = 0; bool valid = false;

    if (warpid < 4) {
        // LSTM warp init: zero my 16 rows of H and C
        const int g = warpid >> 1, w = warpid & 1;
        float* base = s_raw + OFF_GRP + g * GRP_FLOATS;
#pragma unroll
        for (int jj = 0; jj < 16; jj++) {
            int j = w * 16 + jj;
            base[GH + j * 64 + lane] = 0.0f;
            base[GH + j * 64 + 32 + lane] = 0.0f;
            base[GC + j * 64 + lane] = 0.0f;
            base[GC + j * 64 + 32 + lane] = 0.0f;
        }
    } else {
        // Kalman warp init
        const int g = (warpid - 4) >> 1, half = (warpid - 4) & 1;
        const int el = half * 32 + lane;
        int e_raw = blockIdx.x * 128 + g * 64 + el;
        valid = e_raw < B;
        e = valid ? e_raw : (B - 1);
        float2 z0 = hist2[e];
        float2 z1 = hist2[(size_t)B + e];
        X[0] = z0.x; X[1] = (z1.x - z0.x) / dt; X[2] = 0.0f;
        X[3] = (z1.y - z0.y) / dt; X[4] = 0.0f; X[5] = 0.0f;
#pragma unroll
        for (int i = 0; i < 6; i++)
#pragma unroll
            for (int j = 0; j < 6; j++) P[i][j] = 0.0f;
        float d0 = p_psx[0], d1 = p_vsx[0], d2 = p_asx[0];
        float d3 = p_psy[0], d4 = p_vsy[0], d5 = p_asy[0];
        P[0][0] = d0 * d0; P[1][1] = d1 * d1; P[2][2] = d2 * d2;
        P[3][3] = d3 * d3; P[4][4] = d4 * d4; P[5][5] = d5 * d5;
        // publish X(0) into ring slot 0
        float* xw = s_raw + OFF_GRP + g * GRP_FLOATS + GXR;
#pragma unroll
        for (int k = 0; k < 6; k++) xw[k * 64 + el] = X[k];
    }
    __syncthreads();

    if (warpid < 4) {
        // ======================= LSTM warps =======================
        const int g = warpid >> 1, w = warpid & 1;
        float* base = s_raw + OFF_GRP + g * GRP_FLOATS;
        float* FEAT = base + GFEAT;
        float* H    = base + GH;
        float* C    = base + GC;
        const int eA = lane, eB = lane + 32;
        const int TS = 15 + LP;

#pragma unroll 1
        for (int step = 0; step < TS; step++) {
            // top barrier: history chunk ready / pred X ready
            if (step >= 15 || (step % 3) == 0) GROUPBAR(g);

            // ---- feat for my 16 m rows, both elements, from ring slot ----
            {
                const float* xp = base + GXR + (step % 6) * 384;
                float XA[6], XBv[6];
#pragma unroll
                for (int k = 0; k < 6; k++) {
                    XA[k]  = xp[k * 64 + eA];
                    XBv[k] = xp[k * 64 + eB];
                }
                const float4* cf = reinterpret_cast<const float4*>(s_raw + OFF_CF) + w * 32;
#pragma unroll 2
                for (int k = 0; k < 16; k++) {
                    int m = w * 16 + k;
                    float4 a = cf[0];
                    float4 b = cf[1];
                    cf += 2;
                    float accA = b.z, accB = b.z;
                    accA = fmaf(a.x, XA[0], accA);  accB = fmaf(a.x, XBv[0], accB);
                    accA = fmaf(a.y, XA[1], accA);  accB = fmaf(a.y, XBv[1], accB);
                    accA = fmaf(a.z, XA[2], accA);  accB = fmaf(a.z, XBv[2], accB);
                    accA = fmaf(a.w, XA[3], accA);  accB = fmaf(a.w, XBv[3], accB);
                    accA = fmaf(b.x, XA[4], accA);  accB = fmaf(b.x, XBv[4], accB);
                    accA = fmaf(b.y, XA[5], accA);  accB = fmaf(b.y, XBv[5], accB);
                    FEAT[m * 64 + eA] = ftanh(accA);
                    FEAT[m * 64 + eB] = ftanh(accB);
                }
            }
            PAIRBAR(g);   // feat complete (and prior-step H writes visible)

            // ---- gate passes: 2 passes x 8 j, 2 elements per lane ----
            float hA[16], hB[16];
#pragma unroll 1
            for (int pass = 0; pass < 2; pass++) {
                const int jb = w * 16 + pass * 8;
                ull aifA[8], agoA[8], aifB[8], agoB[8];
                {
                    const ulonglong2* sb = reinterpret_cast<const ulonglong2*>(s_raw + OFF_B) + jb;
#pragma unroll
                    for (int jj = 0; jj < 8; jj++) {
                        ulonglong2 b = sb[jj];
                        aifA[jj] = b.x; agoA[jj] = b.y;
                        aifB[jj] = b.x; agoB[jj] = b.y;
                    }
                }
                const ulonglong2* row = reinterpret_cast<const ulonglong2*>(s_raw + OFF_W) + jb;
                const float* fA = FEAT + eA;
                const float* fB = FEAT + eB;
#pragma unroll 2
                for (int m = 0; m < 32; m++) {
                    ull a2A = dup2(fA[m * 64]);
                    ull a2B = dup2(fB[m * 64]);
#pragma unroll
                    for (int jj = 0; jj < 8; jj++) {
                        ulonglong2 ww = row[jj];
                        FMA2(aifA[jj], ww.x, a2A);
                        FMA2(agoA[jj], ww.y, a2A);
                        FMA2(aifB[jj], ww.x, a2B);
                        FMA2(agoB[jj], ww.y, a2B);
                    }
                    row += 32;
                }
                const float* hIA = H + eA;
                const float* hIB = H + eB;
#pragma unroll 2
                for (int m = 0; m < 32; m++) {
                    ull a2A = dup2(hIA[m * 64]);
                    ull a2B = dup2(hIB[m * 64]);
#pragma unroll
                    for (int jj = 0; jj < 8; jj++) {
                        ulonglong2 ww = row[jj];
                        FMA2(aifA[jj], ww.x, a2A);
                        FMA2(agoA[jj], ww.y, a2A);
                        FMA2(aifB[jj], ww.x, a2B);
                        FMA2(agoB[jj], ww.y, a2B);
                    }
                    row += 32;
                }
#pragma unroll
                for (int jj = 0; jj < 8; jj++) {
                    int j = jb + jj;
                    float gi, gf, gg, go;
                    unpack2(aifA[jj], gi, gf);
                    unpack2(agoA[jj], gg, go);
                    float ig = fsig(gi), fg = fsig(gf);
                    float g_ = ftanh(gg), og = fsig(go);
                    float cj = fmaf(fg, C[j * 64 + eA], ig * g_);
                    C[j * 64 + eA] = cj;
                    hA[pass * 8 + jj] = og * ftanh(cj);

                    unpack2(aifB[jj], gi, gf);
                    unpack2(agoB[jj], gg, go);
                    ig = fsig(gi); fg = fsig(gf);
                    g_ = ftanh(gg); og = fsig(go);
                    cj = fmaf(fg, C[j * 64 + eB], ig * g_);
                    C[j * 64 + eB] = cj;
                    hB[pass * 8 + jj] = og * ftanh(cj);
                }
            }
            PAIRBAR(g);   // all H reads (both warps) done

            // ---- write h ----
#pragma unroll
            for (int jj = 0; jj < 16; jj++) {
                int j = w * 16 + jj;
                H[j * 64 + eA] = hA[jj];
                H[j * 64 + eB] = hB[jj];
            }

            // ---- prediction: command partials from registers, then A_k ----
            if (step >= 15) {
                const float4* co4 = reinterpret_cast<const float4*>(s_raw + OFF_CO) + w * 16;
                float p0A = 0.f, p1A = 0.f, p2A = 0.f, p3A = 0.f;
                float p0B = 0.f, p1B = 0.f, p2B = 0.f, p3B = 0.f;
#pragma unroll
                for (int jj = 0; jj < 16; jj++) {
                    float4 cw = co4[jj];
                    p0A = fmaf(cw.x, hA[jj], p0A);
                    p1A = fmaf(cw.y, hA[jj], p1A);
                    p2A = fmaf(cw.z, hA[jj], p2A);
                    p3A = fmaf(cw.w, hA[jj], p3A);
                    p0B = fmaf(cw.x, hB[jj], p0B);
                    p1B = fmaf(cw.y, hB[jj], p1B);
                    p2B = fmaf(cw.z, hB[jj], p2B);
                    p3B = fmaf(cw.w, hB[jj], p3B);
                }
                float* cw_ = base + GCMD + w * 256;
                cw_[0 * 64 + eA] = p0A; cw_[1 * 64 + eA] = p1A;
                cw_[2 * 64 + eA] = p2A; cw_[3 * 64 + eA] = p3A;
                cw_[0 * 64 + eB] = p0B; cw_[1 * 64 + eB] = p1B;
                cw_[2 * 64 + eB] = p2B; cw_[3 * 64 + eB] = p3B;
                GROUPBAR(g);   // A_k : command partials ready
            }
        }
    } else {
        // ======================= Kalman warps =======================
        const int g = (warpid - 4) >> 1, half = (warpid - 4) & 1;
        const int el = half * 32 + lane;
        float* base = s_raw + OFF_GRP + g * GRP_FLOATS;
        const float* KC = s_raw + OFF_K;

        // ---------- history t = 1..15 (runs ahead; barrier per 3-chunk) ----------
#pragma unroll 1
        for (int t = 1; t < 16; t++) {
            {
                float x0 = X[0] + dt * X[1] + hd2 * X[2];
                float x1 = X[1] + dt * X[2];
                float x3 = X[3] + dt * X[4] + hd2 * X[5];
                float x4 = X[4] + dt * X[5];
                X[0] = x0; X[1] = x1; X[3] = x3; X[4] = x4;
            }
#pragma unroll
            for (int cc = 0; cc < 6; cc++) {
                P[0][cc] += dt * P[1][cc] + hd2 * P[2][cc];
                P[1][cc] += dt * P[2][cc];
                P[3][cc] += dt * P[4][cc] + hd2 * P[5][cc];
                P[4][cc] += dt * P[5][cc];
            }
#pragma unroll
            for (int r = 0; r < 6; r++) {
                P[r][0] += dt * P[r][1] + hd2 * P[r][2];
                P[r][1] += dt * P[r][2];
                P[r][3] += dt * P[r][4] + hd2 * P[r][5];
                P[r][4] += dt * P[r][5];
            }
            {
                float gx[3] = {KC[KC_GHX], KC[KC_GHX + 1], KC[KC_GHX + 2]};
                float gy[3] = {KC[KC_GHY], KC[KC_GHY + 1], KC[KC_GHY + 2]};
#pragma unroll
                for (int a = 0; a < 3; a++)
#pragma unroll
                    for (int bb = 0; bb < 3; bb++) {
                        P[a][bb]         += gx[a] * gx[bb];
                        P[3 + a][3 + bb] += gy[a] * gy[bb];
                    }
            }
            float R00 = KC[KC_R], R01 = KC[KC_R + 1], R11 = KC[KC_R + 2];
            float2 z = hist2[(size_t)t * B + e];
            float yx = z.x - X[0], yy = z.y - X[3];
            float S00 = P[0][0] + R00, S01 = P[0][3] + R01;
            float S10 = P[3][0] + R01, S11 = P[3][3] + R11;
            float rdet = 1.0f / (S00 * S11 - S01 * S10);
            float si00 =  S11 * rdet, si01 = -S01 * rdet;
            float si10 = -S10 * rdet, si11 =  S00 * rdet;
            float K0[6], K1[6];
#pragma unroll
            for (int i = 0; i < 6; i++) {
                K0[i] = P[i][0] * si00 + P[i][3] * si10;
                K1[i] = P[i][0] * si01 + P[i][3] * si11;
            }
#pragma unroll
            for (int i = 0; i < 6; i++) X[i] += K0[i] * yx + K1[i] * yy;
            float r0[6], r3[6];
#pragma unroll
            for (int j = 0; j < 6; j++) { r0[j] = P[0][j]; r3[j] = P[3][j]; }
#pragma unroll
            for (int i = 0; i < 6; i++)
#pragma unroll
                for (int j = 0; j < 6; j++) P[i][j] -= K0[i] * r0[j] + K1[i] * r3[j];

            // publish X(t) into ring slot t%6
            float* xw = base + GXR + (t % 6) * 384;
#pragma unroll
            for (int k = 0; k < 6; k++) xw[k * 64 + el] = X[k];
            if ((t % 3) == 2 || t == 15) GROUPBAR(g);   // H1..H6
        }

        // ---------- prediction k = 0..LP-1 ----------
#pragma unroll 1
        for (int k = 0; k < LP; k++) {
            GROUPBAR(g);   // A_k: command partials ready

            float cm0 = base[GCMD + 0 * 64 + el] + base[GCMD + 256 + 0 * 64 + el] + s_raw[OFF_COB + 0];
            float cm1 = base[GCMD + 1 * 64 + el] + base[GCMD + 256 + 1 * 64 + el] + s_raw[OFF_COB + 1];
            float cm2 = base[GCMD + 2 * 64 + el] + base[GCMD + 256 + 2 * 64 + el] + s_raw[OFF_COB + 2];
            float cm3 = base[GCMD + 3 * 64 + el] + base[GCMD + 256 + 3 * 64 + el] + s_raw[OFF_COB + 3];

            // X = F X + B cmd  (critical path)
            {
                float x0 = X[0] + dt * X[1] + hd2 * X[2] + g0 * cm0;
                float x1 = X[1] + dt * X[2] + g1 * cm0;
                float x2 = X[2] + g2 * cm0;
                float x3 = X[3] + dt * X[4] + hd2 * X[5] + g0 * cm1;
                float x4 = X[4] + dt * X[5] + g1 * cm1;
                float x5 = X[5] + g2 * cm1;
                X[0] = x0; X[1] = x1; X[2] = x2; X[3] = x3; X[4] = x4; X[5] = x5;
            }
            if (k < LP - 1) {
                float* xw = base + GXR + ((16 + k) % 6) * 384;
#pragma unroll
                for (int kk = 0; kk < 6; kk++) xw[kk * 64 + el] = X[kk];
                GROUPBAR(g);   // B_k: X ready for next LSTM step
            }

            // off critical path: P update + outputs
            float Gs[6] = {KC[KC_GT + 0] * cm2, KC[KC_GT + 1] * cm2, KC[KC_GT + 2] * cm2,
                           KC[KC_GT + 3] * cm3, KC[KC_GT + 4] * cm3, KC[KC_GT + 5] * cm3};
#pragma unroll
            for (int cc = 0; cc < 6; cc++) {
                P[0][cc] += dt * P[1][cc] + hd2 * P[2][cc];
                P[1][cc] += dt * P[2][cc];
                P[3][cc] += dt * P[4][cc] + hd2 * P[5][cc];
                P[4][cc] += dt * P[5][cc];
            }
#pragma unroll
            for (int r = 0; r < 6; r++) {
                P[r][0] += dt * P[r][1] + hd2 * P[r][2];
                P[r][1] += dt * P[r][2];
                P[r][3] += dt * P[r][4] + hd2 * P[r][5];
                P[r][4] += dt * P[r][5];
            }
#pragma unroll
            for (int i = 0; i < 6; i++)
#pragma unroll
                for (int j = 0; j < 6; j++) P[i][j] += Gs[i] * Gs[j];

            if (valid) {
                float sx = sqrtf(P[0][0]);
                float sy = sqrtf(P[3][3]);
                float rho = __fdividef(P[0][3] + P[3][0], 2.0f * sx * sy);
                size_t o = ((size_t)k * B + e) * 5;
                out[o + 0] = X[0];
                out[o + 1] = X[3];
                out[o + 2] = sx;
                out[o + 3] = sy;
                out[o + 4] = rho;
            }
        }
    }
}

extern "C" void kernel_launch(void* const* d_in, const int* in_sizes, int n_in,
                              void* d_out, int out_size) {
    const float* hist  = (const float*)d_in[0];
    const float* psx   = (const float*)d_in[1];
    const float* psy   = (const float*)d_in[2];
    const float* vsx   = (const float*)d_in[3];
    const float* vsy   = (const float*)d_in[4];
    const float* asx   = (const float*)d_in[5];
    const float* asy   = (const float*)d_in[6];
    const float* jerk  = (const float*)d_in[7];
    const float* coefG = (const float*)d_in[8];
    const float* GR    = (const float*)d_in[9];
    const float* cfW   = (const float*)d_in[10];
    const float* cfb   = (const float*)d_in[11];
    const float* Wih   = (const float*)d_in[12];
    const float* Whh   = (const float*)d_in[13];
    const float* bih   = (const float*)d_in[14];
    const float* bhh   = (const float*)d_in[15];
    const float* coW   = (const float*)d_in[16];
    const float* cob   = (const float*)d_in[17];
    float* out = (float*)d_out;

    const int T = 16;
    int B  = in_sizes[0] / (2 * T);
    int LP = out_size / (B * 5);

    size_t smem = (size_t)SMEM_FLOATS * sizeof(float);  // 106624 bytes
    cudaFuncSetAttribute(kalman_lstm_kernel,
                         cudaFuncAttributeMaxDynamicSharedMemorySize, (int)smem);

    int grid = (B + 127) / 128;   // 128 elements per block
    kalman_lstm_kernel<<<grid, TB, smem>>>(
        hist, psx, psy, vsx, vsy, asx, asy, jerk, coefG, GR,
        cfW, cfb, Wih, Whh, bih, bhh, coW, cob, out, B, LP);
}